// round 2
// baseline (speedup 1.0000x reference)
#include <cuda_runtime.h>
#include <math.h>

// Problem constants
#define Nn 100000
#define Ee 1600000
#define Ss 4
#define Dd 128
#define Hh 256
#define Pp 10000

#define SCAN_BLOCKS 98   // ceil(100000/1024)

// ---------------- scratch (device globals; no allocations) ----------------
__device__ float g_XW1[(size_t)Nn * Hh];   // X @ W1 (snapshot-invariant)
__device__ float g_H1 [(size_t)Nn * Hh];   // relu(layer-1 output)
__device__ float g_HW2[(size_t)Nn * Hh];   // H1 @ W2
__device__ float g_ACC[(size_t)Nn * Hh];   // snapshot accumulator
__device__ float g_DINV[Nn];
__device__ float g_NRM[Ee];                // per-CSR-slot edge norm
__device__ int   g_CNT[Nn];
__device__ int   g_ROWPTR[Nn + 1];
__device__ int   g_CURS[Nn];
__device__ int   g_COL[Ee];                // per-CSR-slot source node
__device__ int   g_BSUM[SCAN_BLOCKS];

// packed fp32x2 FMA (sm_100+): d = a*b + d elementwise on 2-float pairs
__device__ __forceinline__ void fma2(unsigned long long& d,
                                     unsigned long long a,
                                     unsigned long long b) {
    asm("fma.rn.f32x2 %0, %1, %2, %3;" : "=l"(d) : "l"(a), "l"(b), "l"(d));
}

__device__ __forceinline__ void fma4v(float4& a, const float4 v, const float w) {
    a.x = fmaf(v.x, w, a.x); a.y = fmaf(v.y, w, a.y);
    a.z = fmaf(v.z, w, a.z); a.w = fmaf(v.w, w, a.w);
}

// ---------------- SGEMM (f32x2): C[M,256] = A[M,K] @ B[K,256] ----------------
// mode 0: A = param (node_features), C = g_XW1
// mode 1: A = g_H1,                  C = g_HW2
__global__ __launch_bounds__(256) void sgemm_kernel(
    const float* __restrict__ Ap, const float* __restrict__ B,
    int mode, int M, int K)
{
    const int BM = 128, BN = 128, BK = 16;
    // A tile stored transposed AND duplicated {v,v} so the broadcast operand
    // of fma.f32x2 loads directly with no register packing.
    __shared__ float2 As2[BK][BM];   // 16 KB
    __shared__ float  Bs [BK][BN];   // 8 KB

    const float* A = mode ? g_H1 : Ap;
    float*       C = mode ? g_HW2 : g_XW1;
    const int Ncol = Hh;

    int tid = threadIdx.x;                 // 256 threads
    int rowBase = blockIdx.x * BM;
    int colBase = blockIdx.y * BN;
    int tr = tid >> 4;                     // 0..15
    int tc = tid & 15;                     // 0..15

    unsigned long long acc[8][4];          // 8 rows x 8 cols (packed pairs)
#pragma unroll
    for (int i = 0; i < 8; i++)
#pragma unroll
        for (int j = 0; j < 4; j++) acc[i][j] = 0ull;

    for (int k0 = 0; k0 < K; k0 += BK) {
        // A tile 128x16 = 512 float4 (2 per thread), transposed + duplicated
#pragma unroll
        for (int l = 0; l < 2; l++) {
            int f = tid + l * 256;         // 0..511
            int r = f >> 2;                // tile row 0..127
            int cc = (f & 3) * 4;          // tile col 0,4,8,12
            float4 v = make_float4(0.f, 0.f, 0.f, 0.f);
            int gr = rowBase + r;
            if (gr < M)
                v = *reinterpret_cast<const float4*>(&A[(size_t)gr * K + k0 + cc]);
            As2[cc + 0][r] = make_float2(v.x, v.x);
            As2[cc + 1][r] = make_float2(v.y, v.y);
            As2[cc + 2][r] = make_float2(v.z, v.z);
            As2[cc + 3][r] = make_float2(v.w, v.w);
        }
        // B tile 16x128 = 512 float4 (2 per thread)
#pragma unroll
        for (int l = 0; l < 2; l++) {
            int f = tid + l * 256;
            int r = f >> 5;                // 0..15
            int cc = (f & 31) * 4;         // 0..124
            float4 v = *reinterpret_cast<const float4*>(
                &B[(size_t)(k0 + r) * Ncol + colBase + cc]);
            *reinterpret_cast<float4*>(&Bs[r][cc]) = v;
        }
        __syncthreads();

#pragma unroll
        for (int k = 0; k < BK; k++) {
            // 8 duplicated a-values = 4 x LDS.128
            const ulonglong2* ap =
                reinterpret_cast<const ulonglong2*>(&As2[k][tr * 8]);
            ulonglong2 ra01 = ap[0], ra23 = ap[1], ra45 = ap[2], ra67 = ap[3];
            unsigned long long ra[8] = {ra01.x, ra01.y, ra23.x, ra23.y,
                                        ra45.x, ra45.y, ra67.x, ra67.y};
            // 8 b-values (4 packed pairs) = 2 x LDS.128
            const ulonglong2* bp =
                reinterpret_cast<const ulonglong2*>(&Bs[k][tc * 8]);
            ulonglong2 rb01 = bp[0], rb23 = bp[1];
            unsigned long long rb[4] = {rb01.x, rb01.y, rb23.x, rb23.y};

#pragma unroll
            for (int i = 0; i < 8; i++)
#pragma unroll
                for (int j = 0; j < 4; j++)
                    fma2(acc[i][j], ra[i], rb[j]);
        }
        __syncthreads();
    }

#pragma unroll
    for (int i = 0; i < 8; i++) {
        int gr = rowBase + tr * 8 + i;
        if (gr < M) {
            float2 p0 = *reinterpret_cast<float2*>(&acc[i][0]);
            float2 p1 = *reinterpret_cast<float2*>(&acc[i][1]);
            float2 p2 = *reinterpret_cast<float2*>(&acc[i][2]);
            float2 p3 = *reinterpret_cast<float2*>(&acc[i][3]);
            float4 v0 = make_float4(p0.x, p0.y, p1.x, p1.y);
            float4 v1 = make_float4(p2.x, p2.y, p3.x, p3.y);
            float* cp = &C[(size_t)gr * Ncol + colBase + tc * 8];
            *reinterpret_cast<float4*>(cp)     = v0;
            *reinterpret_cast<float4*>(cp + 4) = v1;
        }
    }
}

// ---------------- CSR build ----------------
__global__ void zero_cnt_kernel() {
    int i = blockIdx.x * blockDim.x + threadIdx.x;
    if (i < Nn) g_CNT[i] = 0;
}

__global__ void count_kernel(const int* __restrict__ dst) {
    int e = blockIdx.x * blockDim.x + threadIdx.x;
    if (e < Ee) atomicAdd(&g_CNT[dst[e]], 1);
}

__global__ __launch_bounds__(1024) void scan1_kernel() {
    __shared__ int sh[1024];
    int i = blockIdx.x * 1024 + threadIdx.x;
    int v = (i < Nn) ? g_CNT[i] : 0;
    sh[threadIdx.x] = v;
    __syncthreads();
    for (int off = 1; off < 1024; off <<= 1) {
        int t = 0;
        if (threadIdx.x >= off) t = sh[threadIdx.x - off];
        __syncthreads();
        sh[threadIdx.x] += t;
        __syncthreads();
    }
    if (i < Nn) g_ROWPTR[i] = sh[threadIdx.x] - v;   // exclusive within block
    if (threadIdx.x == 1023) g_BSUM[blockIdx.x] = sh[1023];
}

__global__ void scan2_kernel(int nb) {
    if (threadIdx.x == 0 && blockIdx.x == 0) {
        int s = 0;
        for (int b = 0; b < nb; b++) { int t = g_BSUM[b]; g_BSUM[b] = s; s += t; }
    }
}

__global__ void scan3_kernel() {
    int i = blockIdx.x * blockDim.x + threadIdx.x;
    if (i < Nn) {
        int r = g_ROWPTR[i] + g_BSUM[i >> 10];
        g_ROWPTR[i] = r;
        g_CURS[i]   = r;
        g_DINV[i]   = rsqrtf((float)(g_CNT[i] + 1));
    }
    if (i == 0) g_ROWPTR[Nn] = Ee;
}

__global__ void fill_kernel(const int* __restrict__ src, const int* __restrict__ dst) {
    int e = blockIdx.x * blockDim.x + threadIdx.x;
    if (e < Ee) {
        int d = dst[e], s = src[e];
        int slot = atomicAdd(&g_CURS[d], 1);
        g_COL[slot] = s;
        g_NRM[slot] = g_DINV[s] * g_DINV[d];
    }
}

// ---------------- pull-based GCN aggregation ----------------
// layer 1: H1 = relu( sum_{e->i} XW1[src]*nrm + XW1[i]*dinv^2 + b1 )
__global__ __launch_bounds__(256) void pull_l1_kernel(const float* __restrict__ b1) {
    int warp = (blockIdx.x * blockDim.x + threadIdx.x) >> 5;
    int lane = threadIdx.x & 31;
    if (warp >= Nn) return;
    int i = warp;
    int beg = g_ROWPTR[i], end = g_ROWPTR[i + 1];
    const float4* XW = reinterpret_cast<const float4*>(g_XW1);

    float4 a0 = make_float4(0.f, 0.f, 0.f, 0.f);
    float4 a1 = make_float4(0.f, 0.f, 0.f, 0.f);

    int e = beg;
    for (; e + 3 < end; e += 4) {
        int   s0 = g_COL[e],   s1 = g_COL[e + 1], s2 = g_COL[e + 2], s3 = g_COL[e + 3];
        float w0 = g_NRM[e],   w1 = g_NRM[e + 1], w2 = g_NRM[e + 2], w3 = g_NRM[e + 3];
        float4 v00 = XW[(size_t)s0 * 64 + lane];
        float4 v01 = XW[(size_t)s0 * 64 + 32 + lane];
        float4 v10 = XW[(size_t)s1 * 64 + lane];
        float4 v11 = XW[(size_t)s1 * 64 + 32 + lane];
        float4 v20 = XW[(size_t)s2 * 64 + lane];
        float4 v21 = XW[(size_t)s2 * 64 + 32 + lane];
        float4 v30 = XW[(size_t)s3 * 64 + lane];
        float4 v31 = XW[(size_t)s3 * 64 + 32 + lane];
        fma4v(a0, v00, w0); fma4v(a1, v01, w0);
        fma4v(a0, v10, w1); fma4v(a1, v11, w1);
        fma4v(a0, v20, w2); fma4v(a1, v21, w2);
        fma4v(a0, v30, w3); fma4v(a1, v31, w3);
    }
    for (; e < end; e++) {
        int s0 = g_COL[e]; float w0 = g_NRM[e];
        float4 v0 = XW[(size_t)s0 * 64 + lane];
        float4 v1 = XW[(size_t)s0 * 64 + 32 + lane];
        fma4v(a0, v0, w0); fma4v(a1, v1, w0);
    }

    float di = g_DINV[i];
    float d2 = di * di;
    float4 s0 = XW[(size_t)i * 64 + lane];
    float4 s1 = XW[(size_t)i * 64 + 32 + lane];
    const float4* Bv = reinterpret_cast<const float4*>(b1);
    float4 bb0 = Bv[lane], bb1 = Bv[32 + lane];

    float4 o0, o1;
    o0.x = fmaxf(fmaf(s0.x, d2, a0.x) + bb0.x, 0.f);
    o0.y = fmaxf(fmaf(s0.y, d2, a0.y) + bb0.y, 0.f);
    o0.z = fmaxf(fmaf(s0.z, d2, a0.z) + bb0.z, 0.f);
    o0.w = fmaxf(fmaf(s0.w, d2, a0.w) + bb0.w, 0.f);
    o1.x = fmaxf(fmaf(s1.x, d2, a1.x) + bb1.x, 0.f);
    o1.y = fmaxf(fmaf(s1.y, d2, a1.y) + bb1.y, 0.f);
    o1.z = fmaxf(fmaf(s1.z, d2, a1.z) + bb1.z, 0.f);
    o1.w = fmaxf(fmaf(s1.w, d2, a1.w) + bb1.w, 0.f);

    float4* H = reinterpret_cast<float4*>(g_H1);
    H[(size_t)i * 64 + lane]      = o0;
    H[(size_t)i * 64 + 32 + lane] = o1;
}

// layer 2 + residual + snapshot accumulate:
// ACC (=/+=) sum_{e->i} HW2[src]*nrm + HW2[i]*dinv^2 + b2 + H1[i]
__global__ __launch_bounds__(256) void pull_l2_kernel(const float* __restrict__ b2, int first) {
    int warp = (blockIdx.x * blockDim.x + threadIdx.x) >> 5;
    int lane = threadIdx.x & 31;
    if (warp >= Nn) return;
    int i = warp;
    int beg = g_ROWPTR[i], end = g_ROWPTR[i + 1];
    const float4* HW = reinterpret_cast<const float4*>(g_HW2);

    float4 a0 = make_float4(0.f, 0.f, 0.f, 0.f);
    float4 a1 = make_float4(0.f, 0.f, 0.f, 0.f);

    int e = beg;
    for (; e + 3 < end; e += 4) {
        int   s0 = g_COL[e],   s1 = g_COL[e + 1], s2 = g_COL[e + 2], s3 = g_COL[e + 3];
        float w0 = g_NRM[e],   w1 = g_NRM[e + 1], w2 = g_NRM[e + 2], w3 = g_NRM[e + 3];
        float4 v00 = HW[(size_t)s0 * 64 + lane];
        float4 v01 = HW[(size_t)s0 * 64 + 32 + lane];
        float4 v10 = HW[(size_t)s1 * 64 + lane];
        float4 v11 = HW[(size_t)s1 * 64 + 32 + lane];
        float4 v20 = HW[(size_t)s2 * 64 + lane];
        float4 v21 = HW[(size_t)s2 * 64 + 32 + lane];
        float4 v30 = HW[(size_t)s3 * 64 + lane];
        float4 v31 = HW[(size_t)s3 * 64 + 32 + lane];
        fma4v(a0, v00, w0); fma4v(a1, v01, w0);
        fma4v(a0, v10, w1); fma4v(a1, v11, w1);
        fma4v(a0, v20, w2); fma4v(a1, v21, w2);
        fma4v(a0, v30, w3); fma4v(a1, v31, w3);
    }
    for (; e < end; e++) {
        int s0 = g_COL[e]; float w0 = g_NRM[e];
        float4 v0 = HW[(size_t)s0 * 64 + lane];
        float4 v1 = HW[(size_t)s0 * 64 + 32 + lane];
        fma4v(a0, v0, w0); fma4v(a1, v1, w0);
    }

    float di = g_DINV[i];
    float d2 = di * di;
    float4 s0 = HW[(size_t)i * 64 + lane];
    float4 s1 = HW[(size_t)i * 64 + 32 + lane];
    const float4* Bv = reinterpret_cast<const float4*>(b2);
    float4 bb0 = Bv[lane], bb1 = Bv[32 + lane];
    const float4* H = reinterpret_cast<const float4*>(g_H1);
    float4 h0 = H[(size_t)i * 64 + lane];
    float4 h1 = H[(size_t)i * 64 + 32 + lane];

    float4 r0, r1;
    r0.x = fmaf(s0.x, d2, a0.x) + bb0.x + h0.x;
    r0.y = fmaf(s0.y, d2, a0.y) + bb0.y + h0.y;
    r0.z = fmaf(s0.z, d2, a0.z) + bb0.z + h0.z;
    r0.w = fmaf(s0.w, d2, a0.w) + bb0.w + h0.w;
    r1.x = fmaf(s1.x, d2, a1.x) + bb1.x + h1.x;
    r1.y = fmaf(s1.y, d2, a1.y) + bb1.y + h1.y;
    r1.z = fmaf(s1.z, d2, a1.z) + bb1.z + h1.z;
    r1.w = fmaf(s1.w, d2, a1.w) + bb1.w + h1.w;

    float4* ACC = reinterpret_cast<float4*>(g_ACC);
    size_t i0 = (size_t)i * 64 + lane;
    size_t i1 = (size_t)i * 64 + 32 + lane;
    if (first) {
        ACC[i0] = r0; ACC[i1] = r1;
    } else {
        float4 c0 = ACC[i0], c1 = ACC[i1];
        c0.x += r0.x; c0.y += r0.y; c0.z += r0.z; c0.w += r0.w;
        c1.x += r1.x; c1.y += r1.y; c1.z += r1.z; c1.w += r1.w;
        ACC[i0] = c0; ACC[i1] = c1;
    }
}

// ---------------- classifier: sigmoid(relu(post@Wc1+bc1)@Wc2+bc2) ----------------
__global__ __launch_bounds__(128) void classifier_kernel(
    const int* __restrict__ post_idx,
    const float* __restrict__ Wc1, const float* __restrict__ bc1,
    const float* __restrict__ Wc2, const float* __restrict__ bc2,
    float* __restrict__ out)
{
    __shared__ float post[Hh];
    __shared__ float red[128];
    int p = blockIdx.x;
    int t = threadIdx.x;                    // 128 threads
    int node = post_idx[p];
    const float* row = &g_ACC[(size_t)node * Hh];
    post[t]       = row[t]       * 0.25f;   // mean over S=4 snapshots
    post[t + 128] = row[t + 128] * 0.25f;
    __syncthreads();

    float acc = bc1[t];
#pragma unroll 8
    for (int j = 0; j < Hh; j++)
        acc = fmaf(post[j], Wc1[(size_t)j * 128 + t], acc);
    acc = fmaxf(acc, 0.f);
    float v = acc * Wc2[t];

    red[t] = v;
    __syncthreads();
    for (int off = 64; off > 0; off >>= 1) {
        if (t < off) red[t] += red[t + off];
        __syncthreads();
    }
    if (t == 0) {
        float lg = red[0] + bc2[0];
        out[p] = 1.f / (1.f + expf(-lg));
    }
}

// ---------------- launch ----------------
extern "C" void kernel_launch(void* const* d_in, const int* in_sizes, int n_in,
                              void* d_out, int out_size)
{
    const float* X        = (const float*)d_in[0];
    const int*   EI       = (const int*)  d_in[1];
    const int*   post_idx = (const int*)  d_in[2];
    const float* W1       = (const float*)d_in[3];
    const float* b1       = (const float*)d_in[4];
    const float* W2       = (const float*)d_in[5];
    const float* b2       = (const float*)d_in[6];
    const float* Wc1      = (const float*)d_in[7];
    const float* bc1      = (const float*)d_in[8];
    const float* Wc2      = (const float*)d_in[9];
    const float* bc2      = (const float*)d_in[10];
    float* out = (float*)d_out;

    dim3 gemm_grid((Nn + 127) / 128, Hh / 128);      // (782, 2)
    const int nblk_node = (Nn + 255) / 256;          // 391
    const int nblk_edge = Ee / 256;                  // 6250
    const int nblk_pull = (Nn + 7) / 8;              // 12500 (warp/node, 8 warps/blk)

    // snapshot-invariant: XW1 = X @ W1
    sgemm_kernel<<<gemm_grid, 256>>>(X, W1, 0, Nn, Dd);

    for (int s = 0; s < Ss; s++) {
        const int* src = EI + (size_t)s * 2 * Ee;
        const int* dst = src + Ee;

        zero_cnt_kernel<<<nblk_node, 256>>>();
        count_kernel<<<nblk_edge, 256>>>(dst);
        scan1_kernel<<<SCAN_BLOCKS, 1024>>>();
        scan2_kernel<<<1, 32>>>(SCAN_BLOCKS);
        scan3_kernel<<<nblk_node, 256>>>();
        fill_kernel<<<nblk_edge, 256>>>(src, dst);

        pull_l1_kernel<<<nblk_pull, 256>>>(b1);
        sgemm_kernel<<<gemm_grid, 256>>>(nullptr, W2, 1, Nn, Hh);
        pull_l2_kernel<<<nblk_pull, 256>>>(b2, s == 0 ? 1 : 0);
    }

    classifier_kernel<<<Pp, 128>>>(post_idx, Wc1, bc1, Wc2, bc2, out);
}

// round 4
// speedup vs baseline: 1.2279x; 1.2279x over previous
#include <cuda_runtime.h>
#include <math.h>

// Problem constants
#define Nn 100000
#define Ee 1600000
#define Ss 4
#define Dd 128
#define Hh 256
#define Pp 10000

#define SCAN_BLOCKS 98   // ceil(100000/1024)

// ---------------- scratch (device globals; no allocations) ----------------
__device__ float g_XW1[(size_t)Nn * Hh];   // X @ W1 (snapshot-invariant)
__device__ float g_H1 [(size_t)Nn * Hh];   // relu(layer-1 output)
__device__ float g_HW2[(size_t)Nn * Hh];   // H1 @ W2
__device__ float g_ACC[(size_t)Nn * Hh];   // snapshot accumulator
// double-buffered CSR (built on side stream, consumed on main stream)
__device__ float g_DINV[2][Nn];
__device__ float g_NRM [2][Ee];
__device__ int   g_CNT [2][Nn];
__device__ int   g_ROWPTR[2][Nn + 1];
__device__ int   g_CURS[2][Nn];
__device__ int   g_COL [2][Ee];
__device__ int   g_BSUM[2][SCAN_BLOCKS];

__device__ __forceinline__ void fma4v(float4& a, const float4 v, const float w) {
    a.x = fmaf(v.x, w, a.x); a.y = fmaf(v.y, w, a.y);
    a.z = fmaf(v.z, w, a.z); a.w = fmaf(v.w, w, a.w);
}

// ---------------- SGEMM: C[M,256] = A[M,K] @ B[K,256] (scalar FFMA) --------
// mode 0: A = param (node_features), C = g_XW1
// mode 1: A = g_H1,                  C = g_HW2
__global__ __launch_bounds__(256) void sgemm_kernel(
    const float* __restrict__ Ap, const float* __restrict__ B,
    int mode, int M, int K)
{
    const int BM = 128, BN = 128, BK = 16;
    __shared__ float As[BK][BM];
    __shared__ float Bs[BK][BN];

    const float* A = mode ? g_H1 : Ap;
    float*       C = mode ? g_HW2 : g_XW1;
    const int Ncol = Hh;

    int tid = threadIdx.x;                 // 256 threads
    int rowBase = blockIdx.x * BM;
    int colBase = blockIdx.y * BN;
    int tr = tid >> 4;                     // 0..15
    int tc = tid & 15;                     // 0..15

    float acc[8][8];
#pragma unroll
    for (int i = 0; i < 8; i++)
#pragma unroll
        for (int j = 0; j < 8; j++) acc[i][j] = 0.f;

    for (int k0 = 0; k0 < K; k0 += BK) {
        // A tile 128x16 = 512 float4 (2 per thread), stored transposed
#pragma unroll
        for (int l = 0; l < 2; l++) {
            int f = tid + l * 256;         // 0..511
            int r = f >> 2;                // tile row 0..127
            int cc = (f & 3) * 4;          // tile col 0,4,8,12
            float4 v = make_float4(0.f, 0.f, 0.f, 0.f);
            int gr = rowBase + r;
            if (gr < M)
                v = *reinterpret_cast<const float4*>(&A[(size_t)gr * K + k0 + cc]);
            As[cc + 0][r] = v.x; As[cc + 1][r] = v.y;
            As[cc + 2][r] = v.z; As[cc + 3][r] = v.w;
        }
        // B tile 16x128 = 512 float4 (2 per thread)
#pragma unroll
        for (int l = 0; l < 2; l++) {
            int f = tid + l * 256;
            int r = f >> 5;                // 0..15
            int cc = (f & 31) * 4;         // 0..124
            float4 v = *reinterpret_cast<const float4*>(
                &B[(size_t)(k0 + r) * Ncol + colBase + cc]);
            *reinterpret_cast<float4*>(&Bs[r][cc]) = v;
        }
        __syncthreads();

#pragma unroll
        for (int k = 0; k < BK; k++) {
            float ra[8], rb[8];
#pragma unroll
            for (int i = 0; i < 8; i++) ra[i] = As[k][tr * 8 + i];
#pragma unroll
            for (int j = 0; j < 8; j++) rb[j] = Bs[k][tc * 8 + j];
#pragma unroll
            for (int i = 0; i < 8; i++)
#pragma unroll
                for (int j = 0; j < 8; j++)
                    acc[i][j] = fmaf(ra[i], rb[j], acc[i][j]);
        }
        __syncthreads();
    }

#pragma unroll
    for (int i = 0; i < 8; i++) {
        int gr = rowBase + tr * 8 + i;
        if (gr < M) {
#pragma unroll
            for (int j = 0; j < 8; j += 4) {
                float4 v = make_float4(acc[i][j], acc[i][j + 1],
                                       acc[i][j + 2], acc[i][j + 3]);
                *reinterpret_cast<float4*>(
                    &C[(size_t)gr * Ncol + colBase + tc * 8 + j]) = v;
            }
        }
    }
}

// ---------------- CSR build (buffered) ----------------
__global__ void zero_cnt_kernel(int buf) {
    int i = blockIdx.x * blockDim.x + threadIdx.x;
    if (i < Nn) g_CNT[buf][i] = 0;
}

__global__ void count_kernel(const int* __restrict__ dst, int buf) {
    int e = blockIdx.x * blockDim.x + threadIdx.x;
    if (e < Ee) atomicAdd(&g_CNT[buf][dst[e]], 1);
}

__global__ __launch_bounds__(1024) void scan1_kernel(int buf) {
    __shared__ int sh[1024];
    int i = blockIdx.x * 1024 + threadIdx.x;
    int v = (i < Nn) ? g_CNT[buf][i] : 0;
    sh[threadIdx.x] = v;
    __syncthreads();
    for (int off = 1; off < 1024; off <<= 1) {
        int t = 0;
        if (threadIdx.x >= off) t = sh[threadIdx.x - off];
        __syncthreads();
        sh[threadIdx.x] += t;
        __syncthreads();
    }
    if (i < Nn) g_ROWPTR[buf][i] = sh[threadIdx.x] - v;   // excl within block
    if (threadIdx.x == 1023) g_BSUM[buf][blockIdx.x] = sh[1023];
}

__global__ void scan2_kernel(int buf) {
    if (threadIdx.x == 0 && blockIdx.x == 0) {
        int s = 0;
        for (int b = 0; b < SCAN_BLOCKS; b++) {
            int t = g_BSUM[buf][b]; g_BSUM[buf][b] = s; s += t;
        }
    }
}

__global__ void scan3_kernel(int buf) {
    int i = blockIdx.x * blockDim.x + threadIdx.x;
    if (i < Nn) {
        int r = g_ROWPTR[buf][i] + g_BSUM[buf][i >> 10];
        g_ROWPTR[buf][i] = r;
        g_CURS[buf][i]   = r;
        g_DINV[buf][i]   = rsqrtf((float)(g_CNT[buf][i] + 1));
    }
    if (i == 0) g_ROWPTR[buf][Nn] = Ee;
}

__global__ void fill_kernel(const int* __restrict__ src,
                            const int* __restrict__ dst, int buf) {
    int e = blockIdx.x * blockDim.x + threadIdx.x;
    if (e < Ee) {
        int d = dst[e], s = src[e];
        int slot = atomicAdd(&g_CURS[buf][d], 1);
        g_COL[buf][slot] = s;
        g_NRM[buf][slot] = g_DINV[buf][s] * g_DINV[buf][d];
    }
}

// ---------------- pull-based GCN aggregation ----------------
// layer 1: H1 = relu( sum_{e->i} XW1[src]*nrm + XW1[i]*dinv^2 + b1 )
__global__ __launch_bounds__(256) void pull_l1_kernel(const float* __restrict__ b1,
                                                      int buf) {
    int warp = (blockIdx.x * blockDim.x + threadIdx.x) >> 5;
    int lane = threadIdx.x & 31;
    if (warp >= Nn) return;
    int i = warp;
    int beg = g_ROWPTR[buf][i], end = g_ROWPTR[buf][i + 1];
    const int*   COL = g_COL[buf];
    const float* NRM = g_NRM[buf];
    const float4* XW = reinterpret_cast<const float4*>(g_XW1);

    float4 a0 = make_float4(0.f, 0.f, 0.f, 0.f);
    float4 a1 = make_float4(0.f, 0.f, 0.f, 0.f);

    int e = beg;
    for (; e + 3 < end; e += 4) {
        int   s0 = COL[e],   s1 = COL[e + 1], s2 = COL[e + 2], s3 = COL[e + 3];
        float w0 = NRM[e],   w1 = NRM[e + 1], w2 = NRM[e + 2], w3 = NRM[e + 3];
        float4 v00 = XW[(size_t)s0 * 64 + lane];
        float4 v01 = XW[(size_t)s0 * 64 + 32 + lane];
        float4 v10 = XW[(size_t)s1 * 64 + lane];
        float4 v11 = XW[(size_t)s1 * 64 + 32 + lane];
        float4 v20 = XW[(size_t)s2 * 64 + lane];
        float4 v21 = XW[(size_t)s2 * 64 + 32 + lane];
        float4 v30 = XW[(size_t)s3 * 64 + lane];
        float4 v31 = XW[(size_t)s3 * 64 + 32 + lane];
        fma4v(a0, v00, w0); fma4v(a1, v01, w0);
        fma4v(a0, v10, w1); fma4v(a1, v11, w1);
        fma4v(a0, v20, w2); fma4v(a1, v21, w2);
        fma4v(a0, v30, w3); fma4v(a1, v31, w3);
    }
    for (; e < end; e++) {
        int s0 = COL[e]; float w0 = NRM[e];
        float4 v0 = XW[(size_t)s0 * 64 + lane];
        float4 v1 = XW[(size_t)s0 * 64 + 32 + lane];
        fma4v(a0, v0, w0); fma4v(a1, v1, w0);
    }

    float di = g_DINV[buf][i];
    float d2 = di * di;
    float4 s0 = XW[(size_t)i * 64 + lane];
    float4 s1 = XW[(size_t)i * 64 + 32 + lane];
    const float4* Bv = reinterpret_cast<const float4*>(b1);
    float4 bb0 = Bv[lane], bb1 = Bv[32 + lane];

    float4 o0, o1;
    o0.x = fmaxf(fmaf(s0.x, d2, a0.x) + bb0.x, 0.f);
    o0.y = fmaxf(fmaf(s0.y, d2, a0.y) + bb0.y, 0.f);
    o0.z = fmaxf(fmaf(s0.z, d2, a0.z) + bb0.z, 0.f);
    o0.w = fmaxf(fmaf(s0.w, d2, a0.w) + bb0.w, 0.f);
    o1.x = fmaxf(fmaf(s1.x, d2, a1.x) + bb1.x, 0.f);
    o1.y = fmaxf(fmaf(s1.y, d2, a1.y) + bb1.y, 0.f);
    o1.z = fmaxf(fmaf(s1.z, d2, a1.z) + bb1.z, 0.f);
    o1.w = fmaxf(fmaf(s1.w, d2, a1.w) + bb1.w, 0.f);

    float4* H = reinterpret_cast<float4*>(g_H1);
    H[(size_t)i * 64 + lane]      = o0;
    H[(size_t)i * 64 + 32 + lane] = o1;
}

// layer 2 + residual + snapshot accumulate:
// ACC (=/+=) sum_{e->i} HW2[src]*nrm + HW2[i]*dinv^2 + b2 + H1[i]
__global__ __launch_bounds__(256) void pull_l2_kernel(const float* __restrict__ b2,
                                                      int buf, int first) {
    int warp = (blockIdx.x * blockDim.x + threadIdx.x) >> 5;
    int lane = threadIdx.x & 31;
    if (warp >= Nn) return;
    int i = warp;
    int beg = g_ROWPTR[buf][i], end = g_ROWPTR[buf][i + 1];
    const int*   COL = g_COL[buf];
    const float* NRM = g_NRM[buf];
    const float4* HW = reinterpret_cast<const float4*>(g_HW2);

    float4 a0 = make_float4(0.f, 0.f, 0.f, 0.f);
    float4 a1 = make_float4(0.f, 0.f, 0.f, 0.f);

    int e = beg;
    for (; e + 3 < end; e += 4) {
        int   s0 = COL[e],   s1 = COL[e + 1], s2 = COL[e + 2], s3 = COL[e + 3];
        float w0 = NRM[e],   w1 = NRM[e + 1], w2 = NRM[e + 2], w3 = NRM[e + 3];
        float4 v00 = HW[(size_t)s0 * 64 + lane];
        float4 v01 = HW[(size_t)s0 * 64 + 32 + lane];
        float4 v10 = HW[(size_t)s1 * 64 + lane];
        float4 v11 = HW[(size_t)s1 * 64 + 32 + lane];
        float4 v20 = HW[(size_t)s2 * 64 + lane];
        float4 v21 = HW[(size_t)s2 * 64 + 32 + lane];
        float4 v30 = HW[(size_t)s3 * 64 + lane];
        float4 v31 = HW[(size_t)s3 * 64 + 32 + lane];
        fma4v(a0, v00, w0); fma4v(a1, v01, w0);
        fma4v(a0, v10, w1); fma4v(a1, v11, w1);
        fma4v(a0, v20, w2); fma4v(a1, v21, w2);
        fma4v(a0, v30, w3); fma4v(a1, v31, w3);
    }
    for (; e < end; e++) {
        int s0 = COL[e]; float w0 = NRM[e];
        float4 v0 = HW[(size_t)s0 * 64 + lane];
        float4 v1 = HW[(size_t)s0 * 64 + 32 + lane];
        fma4v(a0, v0, w0); fma4v(a1, v1, w0);
    }

    float di = g_DINV[buf][i];
    float d2 = di * di;
    float4 s0 = HW[(size_t)i * 64 + lane];
    float4 s1 = HW[(size_t)i * 64 + 32 + lane];
    const float4* Bv = reinterpret_cast<const float4*>(b2);
    float4 bb0 = Bv[lane], bb1 = Bv[32 + lane];
    const float4* H = reinterpret_cast<const float4*>(g_H1);
    float4 h0 = H[(size_t)i * 64 + lane];
    float4 h1 = H[(size_t)i * 64 + 32 + lane];

    float4 r0, r1;
    r0.x = fmaf(s0.x, d2, a0.x) + bb0.x + h0.x;
    r0.y = fmaf(s0.y, d2, a0.y) + bb0.y + h0.y;
    r0.z = fmaf(s0.z, d2, a0.z) + bb0.z + h0.z;
    r0.w = fmaf(s0.w, d2, a0.w) + bb0.w + h0.w;
    r1.x = fmaf(s1.x, d2, a1.x) + bb1.x + h1.x;
    r1.y = fmaf(s1.y, d2, a1.y) + bb1.y + h1.y;
    r1.z = fmaf(s1.z, d2, a1.z) + bb1.z + h1.z;
    r1.w = fmaf(s1.w, d2, a1.w) + bb1.w + h1.w;

    float4* ACC = reinterpret_cast<float4*>(g_ACC);
    size_t i0 = (size_t)i * 64 + lane;
    size_t i1 = (size_t)i * 64 + 32 + lane;
    if (first) {
        ACC[i0] = r0; ACC[i1] = r1;
    } else {
        float4 c0 = ACC[i0], c1 = ACC[i1];
        c0.x += r0.x; c0.y += r0.y; c0.z += r0.z; c0.w += r0.w;
        c1.x += r1.x; c1.y += r1.y; c1.z += r1.z; c1.w += r1.w;
        ACC[i0] = c0; ACC[i1] = c1;
    }
}

// ---------------- classifier: sigmoid(relu(post@Wc1+bc1)@Wc2+bc2) ----------------
__global__ __launch_bounds__(128) void classifier_kernel(
    const int* __restrict__ post_idx,
    const float* __restrict__ Wc1, const float* __restrict__ bc1,
    const float* __restrict__ Wc2, const float* __restrict__ bc2,
    float* __restrict__ out)
{
    __shared__ float post[Hh];
    __shared__ float red[128];
    int p = blockIdx.x;
    int t = threadIdx.x;                    // 128 threads
    int node = post_idx[p];
    const float* row = &g_ACC[(size_t)node * Hh];
    post[t]       = row[t]       * 0.25f;   // mean over S=4 snapshots
    post[t + 128] = row[t + 128] * 0.25f;
    __syncthreads();

    float acc = bc1[t];
#pragma unroll 8
    for (int j = 0; j < Hh; j++)
        acc = fmaf(post[j], Wc1[(size_t)j * 128 + t], acc);
    acc = fmaxf(acc, 0.f);
    float v = acc * Wc2[t];

    red[t] = v;
    __syncthreads();
    for (int off = 64; off > 0; off >>= 1) {
        if (t < off) red[t] += red[t + off];
        __syncthreads();
    }
    if (t == 0) {
        float lg = red[0] + bc2[0];
        out[p] = 1.f / (1.f + expf(-lg));
    }
}

// ---------------- launch (side-stream CSR overlap, capture-legal order) ----
static cudaStream_t s_side = nullptr;
static cudaEvent_t  s_evRoot;
static cudaEvent_t  s_evCsr[Ss];
static cudaEvent_t  s_evL2[2];
static cudaEvent_t  s_evJoin;

static void build_csr(const int* EI, int s, cudaStream_t st) {
    const int nblk_node = (Nn + 255) / 256;
    const int nblk_edge = Ee / 256;
    int buf = s & 1;
    const int* src = EI + (size_t)s * 2 * Ee;
    const int* dst = src + Ee;
    zero_cnt_kernel<<<nblk_node, 256, 0, st>>>(buf);
    count_kernel<<<nblk_edge, 256, 0, st>>>(dst, buf);
    scan1_kernel<<<SCAN_BLOCKS, 1024, 0, st>>>(buf);
    scan2_kernel<<<1, 32, 0, st>>>(buf);
    scan3_kernel<<<nblk_node, 256, 0, st>>>(buf);
    fill_kernel<<<nblk_edge, 256, 0, st>>>(src, dst, buf);
}

extern "C" void kernel_launch(void* const* d_in, const int* in_sizes, int n_in,
                              void* d_out, int out_size)
{
    const float* X        = (const float*)d_in[0];
    const int*   EI       = (const int*)  d_in[1];
    const int*   post_idx = (const int*)  d_in[2];
    const float* W1       = (const float*)d_in[3];
    const float* b1       = (const float*)d_in[4];
    const float* W2       = (const float*)d_in[5];
    const float* b2       = (const float*)d_in[6];
    const float* Wc1      = (const float*)d_in[7];
    const float* bc1      = (const float*)d_in[8];
    const float* Wc2      = (const float*)d_in[9];
    const float* bc2      = (const float*)d_in[10];
    float* out = (float*)d_out;

    // one-time host-side resources (created on the uncaptured correctness call)
    if (!s_side) {
        cudaStreamCreateWithFlags(&s_side, cudaStreamNonBlocking);
        cudaEventCreateWithFlags(&s_evRoot, cudaEventDisableTiming);
        for (int s = 0; s < Ss; s++)
            cudaEventCreateWithFlags(&s_evCsr[s], cudaEventDisableTiming);
        for (int s = 0; s < 2; s++)
            cudaEventCreateWithFlags(&s_evL2[s], cudaEventDisableTiming);
        cudaEventCreateWithFlags(&s_evJoin, cudaEventDisableTiming);
    }

    dim3 gemm_grid((Nn + 127) / 128, Hh / 128);      // (782, 2)
    const int nblk_pull = (Nn + 7) / 8;              // 12500 (warp/node)

    // fork side stream from main
    cudaEventRecord(s_evRoot, 0);
    cudaStreamWaitEvent(s_side, s_evRoot, 0);

    // side: CSR(0), CSR(1) — no buffer dependence, overlap with XW1 GEMM
    build_csr(EI, 0, s_side);
    cudaEventRecord(s_evCsr[0], s_side);
    build_csr(EI, 1, s_side);
    cudaEventRecord(s_evCsr[1], s_side);

    // main: XW1 = X @ W1
    sgemm_kernel<<<gemm_grid, 256>>>(X, W1, 0, Nn, Dd);

    for (int s = 0; s < Ss; s++) {
        int buf = s & 1;
        cudaStreamWaitEvent(0, s_evCsr[s], 0);
        pull_l1_kernel<<<nblk_pull, 256>>>(b1, buf);
        sgemm_kernel<<<gemm_grid, 256>>>(nullptr, W2, 1, Nn, Hh);
        pull_l2_kernel<<<nblk_pull, 256>>>(b2, buf, s == 0 ? 1 : 0);
        if (s < 2) {
            // buffer `buf` free after pull_l2(s): build CSR(s+2) on side stream
            cudaEventRecord(s_evL2[s], 0);
            cudaStreamWaitEvent(s_side, s_evL2[s], 0);
            build_csr(EI, s + 2, s_side);
            cudaEventRecord(s_evCsr[s + 2], s_side);
        }
    }

    // join side stream back into main before capture ends
    cudaEventRecord(s_evJoin, s_side);
    cudaStreamWaitEvent(0, s_evJoin, 0);

    classifier_kernel<<<Pp, 128>>>(post_idx, Wc1, bc1, Wc2, bc2, out);
}

// round 5
// speedup vs baseline: 1.5513x; 1.2634x over previous
#include <cuda_runtime.h>
#include <math.h>

// Problem constants
#define Nn 100000
#define Ee 1600000
#define Ss 4
#define Dd 128
#define Hh 256
#define Pp 10000

#define SCAN_BLOCKS 98   // ceil(100000/1024)

// ---------------- scratch (device globals; no allocations) ----------------
__device__ float g_XW1[(size_t)Nn * Hh];       // X @ W1 (snapshot-invariant)
__device__ float g_H1 [2][(size_t)Nn * Hh];    // relu(layer-1), double-buffered
__device__ float g_HW2[2][(size_t)Nn * Hh];    // H1 @ W2, double-buffered
__device__ float g_ACCS[Ss][(size_t)Pp * Hh];  // per-snapshot post embeddings
// double-buffered CSR
__device__ float g_DINV[2][Nn];
__device__ float g_NRM [2][Ee];
__device__ int   g_CNT [2][Nn];
__device__ int   g_ROWPTR[2][Nn + 1];
__device__ int   g_CURS[2][Nn];
__device__ int   g_COL [2][Ee];
__device__ int   g_BSUM[2][SCAN_BLOCKS];

__device__ __forceinline__ void fma4v(float4& a, const float4 v, const float w) {
    a.x = fmaf(v.x, w, a.x); a.y = fmaf(v.y, w, a.y);
    a.z = fmaf(v.z, w, a.z); a.w = fmaf(v.w, w, a.w);
}

// ---------------- SGEMM: C[M,256] = A[M,K] @ B[K,256] (scalar FFMA) --------
// mode 0: A = param (node_features), C = g_XW1
// mode 1: A = g_H1[buf],             C = g_HW2[buf]
__global__ __launch_bounds__(256) void sgemm_kernel(
    const float* __restrict__ Ap, const float* __restrict__ B,
    int mode, int buf, int M, int K)
{
    const int BM = 128, BN = 128, BK = 16;
    __shared__ float As[BK][BM];
    __shared__ float Bs[BK][BN];

    const float* A = mode ? g_H1[buf] : Ap;
    float*       C = mode ? g_HW2[buf] : g_XW1;
    const int Ncol = Hh;

    int tid = threadIdx.x;                 // 256 threads
    int rowBase = blockIdx.x * BM;
    int colBase = blockIdx.y * BN;
    int tr = tid >> 4;                     // 0..15
    int tc = tid & 15;                     // 0..15

    float acc[8][8];
#pragma unroll
    for (int i = 0; i < 8; i++)
#pragma unroll
        for (int j = 0; j < 8; j++) acc[i][j] = 0.f;

    for (int k0 = 0; k0 < K; k0 += BK) {
#pragma unroll
        for (int l = 0; l < 2; l++) {
            int f = tid + l * 256;         // 0..511
            int r = f >> 2;                // tile row 0..127
            int cc = (f & 3) * 4;          // tile col 0,4,8,12
            float4 v = make_float4(0.f, 0.f, 0.f, 0.f);
            int gr = rowBase + r;
            if (gr < M)
                v = *reinterpret_cast<const float4*>(&A[(size_t)gr * K + k0 + cc]);
            As[cc + 0][r] = v.x; As[cc + 1][r] = v.y;
            As[cc + 2][r] = v.z; As[cc + 3][r] = v.w;
        }
#pragma unroll
        for (int l = 0; l < 2; l++) {
            int f = tid + l * 256;
            int r = f >> 5;                // 0..15
            int cc = (f & 31) * 4;         // 0..124
            float4 v = *reinterpret_cast<const float4*>(
                &B[(size_t)(k0 + r) * Ncol + colBase + cc]);
            *reinterpret_cast<float4*>(&Bs[r][cc]) = v;
        }
        __syncthreads();

#pragma unroll
        for (int k = 0; k < BK; k++) {
            float ra[8], rb[8];
#pragma unroll
            for (int i = 0; i < 8; i++) ra[i] = As[k][tr * 8 + i];
#pragma unroll
            for (int j = 0; j < 8; j++) rb[j] = Bs[k][tc * 8 + j];
#pragma unroll
            for (int i = 0; i < 8; i++)
#pragma unroll
                for (int j = 0; j < 8; j++)
                    acc[i][j] = fmaf(ra[i], rb[j], acc[i][j]);
        }
        __syncthreads();
    }

#pragma unroll
    for (int i = 0; i < 8; i++) {
        int gr = rowBase + tr * 8 + i;
        if (gr < M) {
#pragma unroll
            for (int j = 0; j < 8; j += 4) {
                float4 v = make_float4(acc[i][j], acc[i][j + 1],
                                       acc[i][j + 2], acc[i][j + 3]);
                *reinterpret_cast<float4*>(
                    &C[(size_t)gr * Ncol + colBase + tc * 8 + j]) = v;
            }
        }
    }
}

// ---------------- CSR build (buffered) ----------------
__global__ void zero_cnt_kernel(int buf) {
    int i = blockIdx.x * blockDim.x + threadIdx.x;
    if (i < Nn) g_CNT[buf][i] = 0;
}

__global__ void count_kernel(const int* __restrict__ dst, int buf) {
    int e = blockIdx.x * blockDim.x + threadIdx.x;
    if (e < Ee) atomicAdd(&g_CNT[buf][dst[e]], 1);
}

__global__ __launch_bounds__(1024) void scan1_kernel(int buf) {
    __shared__ int sh[1024];
    int i = blockIdx.x * 1024 + threadIdx.x;
    int v = (i < Nn) ? g_CNT[buf][i] : 0;
    sh[threadIdx.x] = v;
    __syncthreads();
    for (int off = 1; off < 1024; off <<= 1) {
        int t = 0;
        if (threadIdx.x >= off) t = sh[threadIdx.x - off];
        __syncthreads();
        sh[threadIdx.x] += t;
        __syncthreads();
    }
    if (i < Nn) g_ROWPTR[buf][i] = sh[threadIdx.x] - v;
    if (threadIdx.x == 1023) g_BSUM[buf][blockIdx.x] = sh[1023];
}

__global__ void scan2_kernel(int buf) {
    if (threadIdx.x == 0 && blockIdx.x == 0) {
        int s = 0;
        for (int b = 0; b < SCAN_BLOCKS; b++) {
            int t = g_BSUM[buf][b]; g_BSUM[buf][b] = s; s += t;
        }
    }
}

__global__ void scan3_kernel(int buf) {
    int i = blockIdx.x * blockDim.x + threadIdx.x;
    if (i < Nn) {
        int r = g_ROWPTR[buf][i] + g_BSUM[buf][i >> 10];
        g_ROWPTR[buf][i] = r;
        g_CURS[buf][i]   = r;
        g_DINV[buf][i]   = rsqrtf((float)(g_CNT[buf][i] + 1));
    }
    if (i == 0) g_ROWPTR[buf][Nn] = Ee;
}

__global__ void fill_kernel(const int* __restrict__ src,
                            const int* __restrict__ dst, int buf) {
    int e = blockIdx.x * blockDim.x + threadIdx.x;
    if (e < Ee) {
        int d = dst[e], s = src[e];
        int slot = atomicAdd(&g_CURS[buf][d], 1);
        g_COL[buf][slot] = s;
        g_NRM[buf][slot] = g_DINV[buf][s] * g_DINV[buf][d];
    }
}

// ---------------- pull layer 1 (all nodes) ----------------
// H1[hbuf] = relu( sum_{e->i} XW1[src]*nrm + XW1[i]*dinv^2 + b1 )
__global__ __launch_bounds__(256) void pull_l1_kernel(const float* __restrict__ b1,
                                                      int buf, int hbuf) {
    int warp = (blockIdx.x * blockDim.x + threadIdx.x) >> 5;
    int lane = threadIdx.x & 31;
    if (warp >= Nn) return;
    int i = warp;
    int beg = g_ROWPTR[buf][i], end = g_ROWPTR[buf][i + 1];
    const int*   COL = g_COL[buf];
    const float* NRM = g_NRM[buf];
    const float4* XW = reinterpret_cast<const float4*>(g_XW1);

    float4 a0 = make_float4(0.f, 0.f, 0.f, 0.f);
    float4 a1 = make_float4(0.f, 0.f, 0.f, 0.f);

    int e = beg;
    for (; e + 3 < end; e += 4) {
        int   s0 = COL[e],   s1 = COL[e + 1], s2 = COL[e + 2], s3 = COL[e + 3];
        float w0 = NRM[e],   w1 = NRM[e + 1], w2 = NRM[e + 2], w3 = NRM[e + 3];
        float4 v00 = XW[(size_t)s0 * 64 + lane];
        float4 v01 = XW[(size_t)s0 * 64 + 32 + lane];
        float4 v10 = XW[(size_t)s1 * 64 + lane];
        float4 v11 = XW[(size_t)s1 * 64 + 32 + lane];
        float4 v20 = XW[(size_t)s2 * 64 + lane];
        float4 v21 = XW[(size_t)s2 * 64 + 32 + lane];
        float4 v30 = XW[(size_t)s3 * 64 + lane];
        float4 v31 = XW[(size_t)s3 * 64 + 32 + lane];
        fma4v(a0, v00, w0); fma4v(a1, v01, w0);
        fma4v(a0, v10, w1); fma4v(a1, v11, w1);
        fma4v(a0, v20, w2); fma4v(a1, v21, w2);
        fma4v(a0, v30, w3); fma4v(a1, v31, w3);
    }
    for (; e < end; e++) {
        int s0 = COL[e]; float w0 = NRM[e];
        float4 v0 = XW[(size_t)s0 * 64 + lane];
        float4 v1 = XW[(size_t)s0 * 64 + 32 + lane];
        fma4v(a0, v0, w0); fma4v(a1, v1, w0);
    }

    float di = g_DINV[buf][i];
    float d2 = di * di;
    float4 s0 = XW[(size_t)i * 64 + lane];
    float4 s1 = XW[(size_t)i * 64 + 32 + lane];
    const float4* Bv = reinterpret_cast<const float4*>(b1);
    float4 bb0 = Bv[lane], bb1 = Bv[32 + lane];

    float4 o0, o1;
    o0.x = fmaxf(fmaf(s0.x, d2, a0.x) + bb0.x, 0.f);
    o0.y = fmaxf(fmaf(s0.y, d2, a0.y) + bb0.y, 0.f);
    o0.z = fmaxf(fmaf(s0.z, d2, a0.z) + bb0.z, 0.f);
    o0.w = fmaxf(fmaf(s0.w, d2, a0.w) + bb0.w, 0.f);
    o1.x = fmaxf(fmaf(s1.x, d2, a1.x) + bb1.x, 0.f);
    o1.y = fmaxf(fmaf(s1.y, d2, a1.y) + bb1.y, 0.f);
    o1.z = fmaxf(fmaf(s1.z, d2, a1.z) + bb1.z, 0.f);
    o1.w = fmaxf(fmaf(s1.w, d2, a1.w) + bb1.w, 0.f);

    float4* H = reinterpret_cast<float4*>(g_H1[hbuf]);
    H[(size_t)i * 64 + lane]      = o0;
    H[(size_t)i * 64 + 32 + lane] = o1;
}

// ---------------- pull layer 2 (POST ROWS ONLY) ----------------
// ACCS[sidx][p] = sum_{e->i} HW2[src]*nrm + HW2[i]*dinv^2 + b2 + H1[i],
// i = post_idx[p]
__global__ __launch_bounds__(256) void pull_l2_kernel(
    const float* __restrict__ b2, const int* __restrict__ post_idx,
    int buf, int hbuf, int sidx)
{
    int warp = (blockIdx.x * blockDim.x + threadIdx.x) >> 5;
    int lane = threadIdx.x & 31;
    if (warp >= Pp) return;
    int p = warp;
    int i = post_idx[p];
    int beg = g_ROWPTR[buf][i], end = g_ROWPTR[buf][i + 1];
    const int*   COL = g_COL[buf];
    const float* NRM = g_NRM[buf];
    const float4* HW = reinterpret_cast<const float4*>(g_HW2[hbuf]);

    float4 a0 = make_float4(0.f, 0.f, 0.f, 0.f);
    float4 a1 = make_float4(0.f, 0.f, 0.f, 0.f);

    int e = beg;
    for (; e + 3 < end; e += 4) {
        int   s0 = COL[e],   s1 = COL[e + 1], s2 = COL[e + 2], s3 = COL[e + 3];
        float w0 = NRM[e],   w1 = NRM[e + 1], w2 = NRM[e + 2], w3 = NRM[e + 3];
        float4 v00 = HW[(size_t)s0 * 64 + lane];
        float4 v01 = HW[(size_t)s0 * 64 + 32 + lane];
        float4 v10 = HW[(size_t)s1 * 64 + lane];
        float4 v11 = HW[(size_t)s1 * 64 + 32 + lane];
        float4 v20 = HW[(size_t)s2 * 64 + lane];
        float4 v21 = HW[(size_t)s2 * 64 + 32 + lane];
        float4 v30 = HW[(size_t)s3 * 64 + lane];
        float4 v31 = HW[(size_t)s3 * 64 + 32 + lane];
        fma4v(a0, v00, w0); fma4v(a1, v01, w0);
        fma4v(a0, v10, w1); fma4v(a1, v11, w1);
        fma4v(a0, v20, w2); fma4v(a1, v21, w2);
        fma4v(a0, v30, w3); fma4v(a1, v31, w3);
    }
    for (; e < end; e++) {
        int s0 = COL[e]; float w0 = NRM[e];
        float4 v0 = HW[(size_t)s0 * 64 + lane];
        float4 v1 = HW[(size_t)s0 * 64 + 32 + lane];
        fma4v(a0, v0, w0); fma4v(a1, v1, w0);
    }

    float di = g_DINV[buf][i];
    float d2 = di * di;
    float4 s0 = HW[(size_t)i * 64 + lane];
    float4 s1 = HW[(size_t)i * 64 + 32 + lane];
    const float4* Bv = reinterpret_cast<const float4*>(b2);
    float4 bb0 = Bv[lane], bb1 = Bv[32 + lane];
    const float4* H = reinterpret_cast<const float4*>(g_H1[hbuf]);
    float4 h0 = H[(size_t)i * 64 + lane];
    float4 h1 = H[(size_t)i * 64 + 32 + lane];

    float4 r0, r1;
    r0.x = fmaf(s0.x, d2, a0.x) + bb0.x + h0.x;
    r0.y = fmaf(s0.y, d2, a0.y) + bb0.y + h0.y;
    r0.z = fmaf(s0.z, d2, a0.z) + bb0.z + h0.z;
    r0.w = fmaf(s0.w, d2, a0.w) + bb0.w + h0.w;
    r1.x = fmaf(s1.x, d2, a1.x) + bb1.x + h1.x;
    r1.y = fmaf(s1.y, d2, a1.y) + bb1.y + h1.y;
    r1.z = fmaf(s1.z, d2, a1.z) + bb1.z + h1.z;
    r1.w = fmaf(s1.w, d2, a1.w) + bb1.w + h1.w;

    float4* ACC = reinterpret_cast<float4*>(g_ACCS[sidx]);
    ACC[(size_t)p * 64 + lane]      = r0;
    ACC[(size_t)p * 64 + 32 + lane] = r1;
}

// ---------------- classifier: sigmoid(relu(mean@Wc1+bc1)@Wc2+bc2) ----------
__global__ __launch_bounds__(128) void classifier_kernel(
    const float* __restrict__ Wc1, const float* __restrict__ bc1,
    const float* __restrict__ Wc2, const float* __restrict__ bc2,
    float* __restrict__ out)
{
    __shared__ float post[Hh];
    __shared__ float red[128];
    int p = blockIdx.x;
    int t = threadIdx.x;                    // 128 threads
    const float* r0 = &g_ACCS[0][(size_t)p * Hh];
    const float* r1 = &g_ACCS[1][(size_t)p * Hh];
    const float* r2 = &g_ACCS[2][(size_t)p * Hh];
    const float* r3 = &g_ACCS[3][(size_t)p * Hh];
    post[t]       = (r0[t]       + r1[t]       + r2[t]       + r3[t])       * 0.25f;
    post[t + 128] = (r0[t + 128] + r1[t + 128] + r2[t + 128] + r3[t + 128]) * 0.25f;
    __syncthreads();

    float acc = bc1[t];
#pragma unroll 8
    for (int j = 0; j < Hh; j++)
        acc = fmaf(post[j], Wc1[(size_t)j * 128 + t], acc);
    acc = fmaxf(acc, 0.f);
    float v = acc * Wc2[t];

    red[t] = v;
    __syncthreads();
    for (int off = 64; off > 0; off >>= 1) {
        if (t < off) red[t] += red[t + off];
        __syncthreads();
    }
    if (t == 0) {
        float lg = red[0] + bc2[0];
        out[p] = 1.f / (1.f + expf(-lg));
    }
}

// ---------------- launch: 3-stream pipelined schedule ----------------
static cudaStream_t s_csr = nullptr;   // CSR builds + pull_l2
static cudaStream_t s_pull = nullptr;  // pull_l1
static cudaEvent_t  s_evRoot, s_evXW1;
static cudaEvent_t  s_evCsr[Ss], s_evPl1[Ss], s_evG[Ss], s_evPl2[Ss];

static void build_csr(const int* EI, int s, cudaStream_t st) {
    const int nblk_node = (Nn + 255) / 256;
    const int nblk_edge = Ee / 256;
    int buf = s & 1;
    const int* src = EI + (size_t)s * 2 * Ee;
    const int* dst = src + Ee;
    zero_cnt_kernel<<<nblk_node, 256, 0, st>>>(buf);
    count_kernel<<<nblk_edge, 256, 0, st>>>(dst, buf);
    scan1_kernel<<<SCAN_BLOCKS, 1024, 0, st>>>(buf);
    scan2_kernel<<<1, 32, 0, st>>>(buf);
    scan3_kernel<<<nblk_node, 256, 0, st>>>(buf);
    fill_kernel<<<nblk_edge, 256, 0, st>>>(src, dst, buf);
}

extern "C" void kernel_launch(void* const* d_in, const int* in_sizes, int n_in,
                              void* d_out, int out_size)
{
    const float* X        = (const float*)d_in[0];
    const int*   EI       = (const int*)  d_in[1];
    const int*   post_idx = (const int*)  d_in[2];
    const float* W1       = (const float*)d_in[3];
    const float* b1       = (const float*)d_in[4];
    const float* W2       = (const float*)d_in[5];
    const float* b2       = (const float*)d_in[6];
    const float* Wc1      = (const float*)d_in[7];
    const float* bc1      = (const float*)d_in[8];
    const float* Wc2      = (const float*)d_in[9];
    const float* bc2      = (const float*)d_in[10];
    float* out = (float*)d_out;

    if (!s_csr) {
        cudaStreamCreateWithFlags(&s_csr, cudaStreamNonBlocking);
        cudaStreamCreateWithFlags(&s_pull, cudaStreamNonBlocking);
        cudaEventCreateWithFlags(&s_evRoot, cudaEventDisableTiming);
        cudaEventCreateWithFlags(&s_evXW1, cudaEventDisableTiming);
        for (int s = 0; s < Ss; s++) {
            cudaEventCreateWithFlags(&s_evCsr[s], cudaEventDisableTiming);
            cudaEventCreateWithFlags(&s_evPl1[s], cudaEventDisableTiming);
            cudaEventCreateWithFlags(&s_evG[s], cudaEventDisableTiming);
            cudaEventCreateWithFlags(&s_evPl2[s], cudaEventDisableTiming);
        }
    }

    dim3 gemm_grid((Nn + 127) / 128, Hh / 128);   // (782, 2)
    const int nblk_pl1 = (Nn + 7) / 8;            // 12500 warps/node blocks
    const int nblk_pl2 = (Pp + 7) / 8;            // 1250

    // fork
    cudaEventRecord(s_evRoot, 0);
    cudaStreamWaitEvent(s_csr, s_evRoot, 0);
    cudaStreamWaitEvent(s_pull, s_evRoot, 0);

    // csr stream: CSR(0), CSR(1)
    build_csr(EI, 0, s_csr);
    cudaEventRecord(s_evCsr[0], s_csr);
    build_csr(EI, 1, s_csr);
    cudaEventRecord(s_evCsr[1], s_csr);

    // main: XW1 = X @ W1
    sgemm_kernel<<<gemm_grid, 256>>>(X, W1, 0, 0, Nn, Dd);
    cudaEventRecord(s_evXW1, 0);

    // pull stream: pl1(0), pl1(1)
    cudaStreamWaitEvent(s_pull, s_evXW1, 0);
    cudaStreamWaitEvent(s_pull, s_evCsr[0], 0);
    pull_l1_kernel<<<nblk_pl1, 256, 0, s_pull>>>(b1, 0, 0);
    cudaEventRecord(s_evPl1[0], s_pull);
    cudaStreamWaitEvent(s_pull, s_evCsr[1], 0);
    pull_l1_kernel<<<nblk_pl1, 256, 0, s_pull>>>(b1, 1, 1);
    cudaEventRecord(s_evPl1[1], s_pull);

    for (int s = 0; s < Ss; s++) {
        int buf = s & 1;
        // main: gemm(s) — needs pl1(s); HW2[buf] free (pl2(s-2) waited via pl1 chain)
        cudaStreamWaitEvent(0, s_evPl1[s], 0);
        if (s >= 2) cudaStreamWaitEvent(0, s_evPl2[s - 2], 0);
        sgemm_kernel<<<gemm_grid, 256>>>(nullptr, W2, 1, buf, Nn, Hh);
        cudaEventRecord(s_evG[s], 0);

        // csr stream: pl2(s) after gemm(s) (CSR(s) already in-order on s_csr)
        cudaStreamWaitEvent(s_csr, s_evG[s], 0);
        pull_l2_kernel<<<nblk_pl2, 256, 0, s_csr>>>(b2, post_idx, buf, buf, s);
        cudaEventRecord(s_evPl2[s], s_csr);

        if (s + 2 < Ss) {
            // csr stream: CSR(s+2) reuses csr buf — needs pl1(s) done (pl2(s) in-order)
            cudaStreamWaitEvent(s_csr, s_evPl1[s], 0);
            build_csr(EI, s + 2, s_csr);
            cudaEventRecord(s_evCsr[s + 2], s_csr);

            // pull stream: pl1(s+2) — needs CSR(s+2), and H1[buf] free:
            // gemm(s) done (read) and pl2(s) done (residual read)
            cudaStreamWaitEvent(s_pull, s_evCsr[s + 2], 0);
            cudaStreamWaitEvent(s_pull, s_evG[s], 0);
            cudaStreamWaitEvent(s_pull, s_evPl2[s], 0);
            pull_l1_kernel<<<nblk_pl1, 256, 0, s_pull>>>(b1, buf, buf);
            cudaEventRecord(s_evPl1[s + 2], s_pull);
        }
    }

    // join: classifier needs all pl2
    for (int s = 0; s < Ss; s++)
        cudaStreamWaitEvent(0, s_evPl2[s], 0);
    classifier_kernel<<<Pp, 128>>>(Wc1, bc1, Wc2, bc2, out);
}